// round 3
// baseline (speedup 1.0000x reference)
#include <cuda_runtime.h>
#include <cuda_bf16.h>

// BCELoss(reduce=False) with "correct-side" masking.
//   y in {0,1}. q = y ? p : 1-p.  loss = (q > 0.5) ? 0 : -max(log q, -100)
// log(1-p) only evaluated when p >= 0.5 -> 1-p exact (Sterbenz), matches
// reference log1p(-p) to fp32 precision.

__device__ __forceinline__ float bce_elem(float p, float y) {
    float q = (y > 0.5f) ? p : (1.0f - p);
    if (q > 0.5f) return 0.0f;
    float l = fmaxf(__logf(q), -100.0f);
    return -l;
}

__global__ void __launch_bounds__(256)
neo_loss_vec4(const float4* __restrict__ pred,
              const float4* __restrict__ actual,
              float4* __restrict__ out,
              int n4) {
    int i = blockIdx.x * blockDim.x + threadIdx.x;
    if (i >= n4) return;
    float4 p = pred[i];
    float4 y = actual[i];
    float4 o;
    o.x = bce_elem(p.x, y.x);
    o.y = bce_elem(p.y, y.y);
    o.z = bce_elem(p.z, y.z);
    o.w = bce_elem(p.w, y.w);
    out[i] = o;
}

__global__ void neo_loss_tail(const float* __restrict__ pred,
                              const float* __restrict__ actual,
                              float* __restrict__ out,
                              int start, int n) {
    int i = start + blockIdx.x * blockDim.x + threadIdx.x;
    if (i >= n) return;
    out[i] = bce_elem(pred[i], actual[i]);
}

extern "C" void kernel_launch(void* const* d_in, const int* in_sizes, int n_in,
                              void* d_out, int out_size) {
    const float* pred   = (const float*)d_in[0];
    const float* actual = (const float*)d_in[1];
    float* out = (float*)d_out;
    int n = in_sizes[0];

    int n4 = n >> 2;            // float4 count
    int vec_elems = n4 << 2;

    if (n4 > 0) {
        int threads = 256;
        int blocks = (n4 + threads - 1) / threads;
        neo_loss_vec4<<<blocks, threads>>>(
            (const float4*)pred, (const float4*)actual, (float4*)out, n4);
    }
    if (vec_elems < n) {
        int rem = n - vec_elems;
        neo_loss_tail<<<(rem + 255) / 256, 256>>>(pred, actual, out, vec_elems, n);
    }
}